// round 17
// baseline (speedup 1.0000x reference)
#include <cuda_runtime.h>
#include <math_constants.h>

#define B_   4
#define C_   84
#define CR_  80          // channels participating in the max (84 - 4)
#define H_   512
#define W_   512
#define HW_  (H_ * W_)

#define CW   64          // columns per block strip
#define TH   16          // output rows per block
#define NW   7           // warps; warp w owns channels [12w, 12w+12) (6 pairs)
#define NPAIR 6
#define NT   224
#define RING 4

// ---------------------------------------------------------------------------
// Fused NMS: float4 paired loads (512B warp transactions) + register-carried
// values (no reload, no smem value buffer). Traffic at the compulsory floor
// with R16's proven ~79% DRAM utilization.
//
// Block = 64-col x 16-row strip of one batch; 7 warps; warp w owns channel
// pairs (12w+2i, 12w+2i+1), i<6 -> all 84 channels. Lane layout: half=lane>>4
// selects the channel of the pair, lx=lane&15 selects cols 4lx..4lx+3. One
// LDG.128 per (warp,i) moves 2 channels x 64 cols = 512B (two dense 256B
// segments).
//
// Per output row h (ONE barrier):
//   load row h+1: 6 paired float4 -> regs w4[], running max over channels
//     <80 -> cross-half shuffle -> pbq ring slot (h+1)&3 (per-warp partial).
//     Warps 0/1 also gather the two halo-column 80-ch maxes -> ph ring.
//   __syncthreads();
//   mask row h: combine 7 warp-partials (+halo cols / shuffled neighbors),
//     reference semantics: strict > for row-above + left, >= for right +
//     row-below; zero padding. Multiply carried v4[] -> streaming stores.
//   v4 = w4.
//
// Ring safety (RING=4): iter h writes slot (h+1)&3 pre-barrier (warp-private
// regions), reads slots (h-1..h+1)&3 post-barrier; a fast warp's next write
// is (h+2)&3 - disjoint. One barrier per row suffices.
// ---------------------------------------------------------------------------
__global__ void __launch_bounds__(NT, 4) fused_nms_vcarry(
    const float* __restrict__ points, float* __restrict__ out)
{
    __shared__ float4 pbq[RING][NW][CW / 4];  // per-warp partial col maxes
    __shared__ float  ph[RING][2];            // halo-column combined maxes

    const int tid  = threadIdx.x;
    const int wp   = tid >> 5;                // 0..6
    const int lane = tid & 31;
    const int half = lane >> 4;               // channel within pair
    const int lx   = lane & 15;               // float4 col group
    const int x0   = blockIdx.x * CW;
    const int h0   = blockIdx.y * TH;
    const int b    = blockIdx.z;
    const size_t bbase = (size_t)b * C_ * HW_;

    const float* inb  = points + bbase + x0 + 4 * lx;
    float*       outb = out    + bbase + x0 + 4 * lx;

    // ---- shared probs bookkeeping (partial max m4 already computed) ------
    auto probs_commit = [&](int g, float4 m4) {
        const int s = g & (RING - 1);
        m4.x = fmaxf(m4.x, __shfl_xor_sync(0xffffffffu, m4.x, 16));
        m4.y = fmaxf(m4.y, __shfl_xor_sync(0xffffffffu, m4.y, 16));
        m4.z = fmaxf(m4.z, __shfl_xor_sync(0xffffffffu, m4.z, 16));
        m4.w = fmaxf(m4.w, __shfl_xor_sync(0xffffffffu, m4.w, 16));
        if (half == 0) pbq[s][wp][lx] = m4;

        if (wp < 2) {                         // halo cols x0-1 / x0+CW
            const int hx = (wp == 0) ? (x0 - 1) : (x0 + CW);
            float hm = 0.f;
            if (g >= 0 && g < H_ && hx >= 0 && hx < W_) {
                hm = -CUDART_INF_F;
                const float* hp = points + bbase + (size_t)g * W_ + hx;
                #pragma unroll
                for (int k = 0; k < 3; k++) {
                    const int c = lane + k * 32;
                    if (c < CR_) hm = fmaxf(hm, __ldg(hp + (size_t)c * HW_));
                }
                #pragma unroll
                for (int off = 16; off; off >>= 1)
                    hm = fmaxf(hm, __shfl_xor_sync(0xffffffffu, hm, off));
            }
            if (lane == 0) ph[s][wp] = hm;
        }
    };

    // ---- probs-only row (halo / pad): load only channels < 80 ------------
    auto probs_only_row = [&](int g) {
        float4 m4 = make_float4(0.f, 0.f, 0.f, 0.f);     // pad value
        if (g >= 0 && g < H_) {
            m4 = make_float4(-CUDART_INF_F, -CUDART_INF_F,
                             -CUDART_INF_F, -CUDART_INF_F);
            const float* rp = inb + (size_t)g * W_;
            #pragma unroll
            for (int i = 0; i < NPAIR; i++) {
                const int c = 12 * wp + 2 * i + half;
                if (c < CR_) {
                    float4 v = __ldg(reinterpret_cast<const float4*>(
                                         rp + (size_t)c * HW_));
                    m4.x = fmaxf(m4.x, v.x); m4.y = fmaxf(m4.y, v.y);
                    m4.z = fmaxf(m4.z, v.z); m4.w = fmaxf(m4.w, v.w);
                }
            }
        }
        probs_commit(g, m4);
    };

    // ---- full row load -> buf[], probs commit ----------------------------
    auto full_row = [&](int g, float4* buf) {
        const float* rp = inb + (size_t)g * W_;
        float4 m4 = make_float4(-CUDART_INF_F, -CUDART_INF_F,
                                -CUDART_INF_F, -CUDART_INF_F);
        #pragma unroll
        for (int i = 0; i < NPAIR; i++) {
            const int c = 12 * wp + 2 * i + half;
            float4 v = __ldg(reinterpret_cast<const float4*>(
                                 rp + (size_t)c * HW_));
            buf[i] = v;
            if (c < CR_) {
                m4.x = fmaxf(m4.x, v.x); m4.y = fmaxf(m4.y, v.y);
                m4.z = fmaxf(m4.z, v.z); m4.w = fmaxf(m4.w, v.w);
            }
        }
        probs_commit(g, m4);
    };

    // 7-way combined probs float4 at ring slot s for this lane's 4 cols
    auto qmax = [&](int s) -> float4 {
        float4 r = pbq[s][0][lx];
        #pragma unroll
        for (int w2 = 1; w2 < NW; w2++) {
            float4 t = pbq[s][w2][lx];
            r.x = fmaxf(r.x, t.x); r.y = fmaxf(r.y, t.y);
            r.z = fmaxf(r.z, t.z); r.w = fmaxf(r.w, t.w);
        }
        return r;
    };

    float4 v4[NPAIR], w4[NPAIR];

    // ---- prologue ---------------------------------------------------------
    probs_only_row(h0 - 1);
    full_row(h0, v4);

    // ---- main pipeline: one barrier per row -------------------------------
    for (int h = h0; h < h0 + TH; h++) {
        const int gn = h + 1;
        if (gn < h0 + TH) full_row(gn, w4);
        else              probs_only_row(gn);
        __syncthreads();

        const int s0 = (h - 1) & (RING - 1);
        const int s1 = h       & (RING - 1);
        const int s2 = (h + 1) & (RING - 1);

        // rows as 6-wide: [0]=left nb, [1..4]=this lane's cols, [5]=right nb
        float a0[6], a1[6], a2[6];
        {
            float4 c0 = qmax(s0), c1 = qmax(s1), c2 = qmax(s2);
            a0[1] = c0.x; a0[2] = c0.y; a0[3] = c0.z; a0[4] = c0.w;
            a1[1] = c1.x; a1[2] = c1.y; a1[3] = c1.z; a1[4] = c1.w;
            a2[1] = c2.x; a2[2] = c2.y; a2[3] = c2.z; a2[4] = c2.w;
            float l0 = __shfl_up_sync(0xffffffffu, c0.w, 1);
            float l1 = __shfl_up_sync(0xffffffffu, c1.w, 1);
            float l2 = __shfl_up_sync(0xffffffffu, c2.w, 1);
            float r0 = __shfl_down_sync(0xffffffffu, c0.x, 1);
            float r1 = __shfl_down_sync(0xffffffffu, c1.x, 1);
            float r2 = __shfl_down_sync(0xffffffffu, c2.x, 1);
            a0[0] = (lx == 0)  ? ph[s0][0] : l0;
            a1[0] = (lx == 0)  ? ph[s1][0] : l1;
            a2[0] = (lx == 0)  ? ph[s2][0] : l2;
            a0[5] = (lx == 15) ? ph[s0][1] : r0;
            a1[5] = (lx == 15) ? ph[s1][1] : r1;
            a2[5] = (lx == 15) ? ph[s2][1] : r2;
        }

        float mkv[4];
        #pragma unroll
        for (int j = 0; j < 4; j++) {
            const float p = a1[j + 1];
            bool ok =
                (p >  a0[j    ]) &&   // (-1,-1)
                (p >  a0[j + 1]) &&   // (-1, 0)
                (p >  a0[j + 2]) &&   // (-1,+1)
                (p >  a1[j    ]) &&   // ( 0,-1) left
                (p >= a1[j + 2]) &&   // ( 0,+1) right
                (p >= a2[j    ]) &&   // (+1,-1)
                (p >= a2[j + 1]) &&   // (+1, 0)
                (p >= a2[j + 2]);     // (+1,+1)
            mkv[j] = ok ? 1.0f : 0.0f;
        }

        // store carried row h (no reload)
        float* op = outb + (size_t)h * W_;
        #pragma unroll
        for (int i = 0; i < NPAIR; i++) {
            const int c = 12 * wp + 2 * i + half;
            float4 v = v4[i];
            v.x *= mkv[0]; v.y *= mkv[1]; v.z *= mkv[2]; v.w *= mkv[3];
            __stcs(reinterpret_cast<float4*>(op + (size_t)c * HW_), v);
        }

        if (gn < h0 + TH) {
            #pragma unroll
            for (int i = 0; i < NPAIR; i++) v4[i] = w4[i];
        }
        // next probs write targets slot (h+2)&3 — disjoint from reads above.
    }
}

// ---------------------------------------------------------------------------
extern "C" void kernel_launch(void* const* d_in, const int* in_sizes, int n_in,
                              void* d_out, int out_size)
{
    const float* points = (const float*)d_in[0];
    float* out = (float*)d_out;

    dim3 grid(W_ / CW, H_ / TH, B_);   // (8, 32, 4) = 1024 blocks
    fused_nms_vcarry<<<grid, NT>>>(points, out);
}